// round 11
// baseline (speedup 1.0000x reference)
#include <cuda_runtime.h>
#include <cstdint>

// GRU_12962211299468 : B=65536, T=9, I=57, H=2, O=1, fp32
// Round 11: single fused kernel. CTA = 288 threads (9 warps) owns 32 whole
// batch elements = 65664 contiguous bytes of x.
//   stage:  cp.async.cg of the full 65.7 KB tile (all threads, ~15 chunks ea)
//   project: warp w = timestep w; lane = batch; row LDS stride 513 (odd,
//            conflict-free); weights broadcast LDS.128; gates -> smem sgx
//   recur:  warp 0, lane = batch, 9-step recurrence + FC, coalesced store
// No gx scratch round-trip (saves 28.4 MB traffic + a kernel launch).

#define T_STEPS 9
#define I_DIM   57
#define B_TOT   65536
#define NB      32                          // batches per CTA
#define NTHR    (NB * T_STEPS)              // 288 threads = 9 warps
#define XFLT    (NB * T_STEPS * I_DIM)      // 16416 floats = 65664 B
#define XV4     (XFLT / 4)                  // 4104 16-B chunks
#define WROW    60                          // padded W_ih row
#define SGXROW  57                          // sgx row stride (odd: conflict-free)
#define GRID    (B_TOT / NB)                // 2048 CTAs

// dynamic smem layout (floats):
//   [0, XFLT)                       x tile
//   [XFLT, XFLT+6*WROW)             W_ih padded
//   [XFLT+6*WROW, +NB*SGXROW)       sgx gates
#define SW_OFF  XFLT
#define SGX_OFF (XFLT + 6 * WROW)
#define SMEM_FLOATS (SGX_OFF + NB * SGXROW)
#define SMEM_BYTES  (SMEM_FLOATS * 4)       // 74400 B

__device__ __forceinline__ uint32_t s2u(const void* p) {
    uint32_t a;
    asm("{ .reg .u64 t; cvta.to.shared.u64 t, %1; cvt.u32.u64 %0, t; }"
        : "=r"(a) : "l"(p));
    return a;
}
__device__ __forceinline__ void cp16(uint32_t dst, const float4* src) {
    asm volatile("cp.async.cg.shared.global [%0], [%1], 16;"
                 :: "r"(dst), "l"(src) : "memory");
}
__device__ __forceinline__ void cp_commit_wait0() {
    asm volatile("cp.async.commit_group;" ::: "memory");
    asm volatile("cp.async.wait_group 0;" ::: "memory");
}

__device__ __forceinline__ float sigf(float v) {
    return 1.0f / (1.0f + __expf(-v));
}
__device__ __forceinline__ float tanh_ex(float v) {
    return 1.0f - 2.0f / (__expf(2.0f * v) + 1.0f);
}

__global__ __launch_bounds__(NTHR, 3) void gru_fused(
    const float* __restrict__ x,
    const float* __restrict__ Wih,   // [6,57]
    const float* __restrict__ Whh,   // [6,2]
    const float* __restrict__ bih,   // [6]
    const float* __restrict__ bhh,   // [6]
    const float* __restrict__ fcw,   // [2]
    const float* __restrict__ fcb,   // [1]
    float* __restrict__ out)         // [B]
{
    extern __shared__ __align__(16) float sm[];
    float* sx  = sm;                 // x tile
    float* sw  = sm + SW_OFF;        // W_ih padded
    float* sgx = sm + SGX_OFF;       // gate pre-activations

    const int tid  = threadIdx.x;
    const int wid  = tid >> 5;       // timestep this warp projects
    const int lane = tid & 31;       // batch within CTA
    const int b0   = blockIdx.x * NB;

    // ---- stage x tile: 4104 cp.async chunks, fully contiguous ----
    {
        const float4* src = reinterpret_cast<const float4*>(x) +
                            (size_t)blockIdx.x * XV4;
        const uint32_t sb = s2u(sx);
#pragma unroll
        for (int k = 0; k < 15; ++k) {
            int j = tid + NTHR * k;
            if (j < XV4) cp16(sb + 16u * (uint32_t)j, src + j);
        }
    }

    // ---- stage W_ih (padded rows) while cp.async is in flight ----
    for (int j = tid; j < 6 * WROW; j += NTHR) {
        int g = j / WROW;
        int i = j - g * WROW;
        sw[j] = (i < I_DIM) ? Wih[g * I_DIM + i] : 0.0f;
    }

    cp_commit_wait0();
    __syncthreads();

    // ---- projection: warp wid handles t=wid for all 32 batches ----
    {
        const float* row = &sx[lane * (T_STEPS * I_DIM) + wid * I_DIM];
        // lane stride 513 floats (odd) -> conflict-free scalar LDS

        float g0 = bih[0], g1 = bih[1], g2 = bih[2];
        float g3 = bih[3], g4 = bih[4], g5 = bih[5];

#pragma unroll
        for (int c = 0; c < 14; ++c) {
            float x0 = row[4 * c + 0];
            float x1 = row[4 * c + 1];
            float x2 = row[4 * c + 2];
            float x3 = row[4 * c + 3];
            float4 v;
            v = *reinterpret_cast<const float4*>(&sw[0 * WROW + 4 * c]);
            g0 += v.x * x0 + v.y * x1 + v.z * x2 + v.w * x3;
            v = *reinterpret_cast<const float4*>(&sw[1 * WROW + 4 * c]);
            g1 += v.x * x0 + v.y * x1 + v.z * x2 + v.w * x3;
            v = *reinterpret_cast<const float4*>(&sw[2 * WROW + 4 * c]);
            g2 += v.x * x0 + v.y * x1 + v.z * x2 + v.w * x3;
            v = *reinterpret_cast<const float4*>(&sw[3 * WROW + 4 * c]);
            g3 += v.x * x0 + v.y * x1 + v.z * x2 + v.w * x3;
            v = *reinterpret_cast<const float4*>(&sw[4 * WROW + 4 * c]);
            g4 += v.x * x0 + v.y * x1 + v.z * x2 + v.w * x3;
            v = *reinterpret_cast<const float4*>(&sw[5 * WROW + 4 * c]);
            g5 += v.x * x0 + v.y * x1 + v.z * x2 + v.w * x3;
        }
        {
            float xs = row[56];
            g0 += sw[0 * WROW + 56] * xs;
            g1 += sw[1 * WROW + 56] * xs;
            g2 += sw[2 * WROW + 56] * xs;
            g3 += sw[3 * WROW + 56] * xs;
            g4 += sw[4 * WROW + 56] * xs;
            g5 += sw[5 * WROW + 56] * xs;
        }

        // gates for (batch=lane, t=wid): stride 57 rows -> conflict-free STS
        float* gq = &sgx[lane * SGXROW + 6 * wid];
        gq[0] = g0; gq[1] = g1; gq[2] = g2;
        gq[3] = g3; gq[4] = g4; gq[5] = g5;
    }
    __syncthreads();

    // ---- recurrence + FC: warp 0, lane = batch ----
    if (wid == 0) {
        const float w00 = Whh[0],  w01 = Whh[1];
        const float w10 = Whh[2],  w11 = Whh[3];
        const float w20 = Whh[4],  w21 = Whh[5];
        const float w30 = Whh[6],  w31 = Whh[7];
        const float w40 = Whh[8],  w41 = Whh[9];
        const float w50 = Whh[10], w51 = Whh[11];
        const float bh0 = bhh[0], bh1 = bhh[1], bh2 = bhh[2];
        const float bh3 = bhh[3], bh4 = bhh[4], bh5 = bhh[5];

        const float* gp = &sgx[lane * SGXROW];   // stride 57: conflict-free
        float h0 = 0.0f, h1 = 0.0f;

#pragma unroll
        for (int t = 0; t < T_STEPS; ++t) {
            float q0 = gp[6 * t + 0];
            float q1 = gp[6 * t + 1];
            float q2 = gp[6 * t + 2];
            float q3 = gp[6 * t + 3];
            float q4 = gp[6 * t + 4];
            float q5 = gp[6 * t + 5];

            float a0 = w00 * h0 + w01 * h1 + bh0;
            float a1 = w10 * h0 + w11 * h1 + bh1;
            float a2 = w20 * h0 + w21 * h1 + bh2;
            float a3 = w30 * h0 + w31 * h1 + bh3;
            float a4 = w40 * h0 + w41 * h1 + bh4;
            float a5 = w50 * h0 + w51 * h1 + bh5;

            float r0 = sigf(q0 + a0);
            float r1 = sigf(q1 + a1);
            float z0 = sigf(q2 + a2);
            float z1 = sigf(q3 + a3);
            float n0 = tanh_ex(q4 + r0 * a4);
            float n1 = tanh_ex(q5 + r1 * a5);

            h0 = (1.0f - z0) * n0 + z0 * h0;
            h1 = (1.0f - z1) * n1 + z1 * h1;
        }

        out[b0 + lane] = fcw[0] * h0 + fcw[1] * h1 + fcb[0];   // coalesced
    }
}

extern "C" void kernel_launch(void* const* d_in, const int* in_sizes, int n_in,
                              void* d_out, int out_size) {
    const float* x   = (const float*)d_in[0];
    const float* Wih = (const float*)d_in[1];
    const float* Whh = (const float*)d_in[2];
    const float* bih = (const float*)d_in[3];
    const float* bhh = (const float*)d_in[4];
    const float* fcw = (const float*)d_in[5];
    const float* fcb = (const float*)d_in[6];
    float* out = (float*)d_out;

    (void)in_sizes; (void)n_in; (void)out_size;

    static int configured = 0;
    if (!configured) {
        cudaFuncSetAttribute(gru_fused,
                             cudaFuncAttributeMaxDynamicSharedMemorySize,
                             SMEM_BYTES);
        configured = 1;
    }

    gru_fused<<<GRID, NTHR, SMEM_BYTES>>>(x, Wih, Whh, bih, bhh, fcw, fcb, out);
}